// round 6
// baseline (speedup 1.0000x reference)
#include <cuda_runtime.h>
#include <cstdint>

// ---------------------------------------------------------------------------
// AnisotropicDistance: out[b,i,j] = alpha_i * max(||d||^2 + a^2*(|t_i|^2-2), 0)
//                                 + beta_i * a^2,  d = p_i - p_j, a = d . t_i
// B=2, N=8192 -> 537MB fp32 output: DRAM-write bound.
// R5 -> R6: store issue cost was the wall (4x STG.32/row, 5cyc each).
//  - STG.128: thread owns 4 consecutive cols, one float4 streaming store/row.
//  - fma.rn.f32x2 packed over ROW-PAIRS: row constants come pre-packed from
//    the pack kernel (zero runtime packing); j-side {v,v} packs hoisted.
//    ~7.5 instr/element vs 11.
// ---------------------------------------------------------------------------

#define MAX_BN 32768

__device__ float4 g_pack[MAX_BN];   // (px, py, pz, |p|^2) -- j-side data

// Row-PAIR constants, pre-packed for f32x2 math (rows 2q and 2q+1 interleaved)
struct __align__(16) RowPair {
    float4 q0;  // {Ax0,Ax1, Ay0,Ay1}   A = -t
    float4 q1;  // {Az0,Az1, Aw0,Aw1}   Aw = p.t
    float4 q2;  // {Bx0,Bx1, By0,By1}   B = -2p
    float4 q3;  // {Bz0,Bz1, Bw0,Bw1}   Bw = |p|^2
    float4 q4;  // {Cx0,Cx1, al0,al1}   Cx = |t|^2-2, al = 2(1+lin)
    float4 q5;  // {be0,be1, 0, 0}      be = 0.5(1-lin)
};
__device__ RowPair g_rp[MAX_BN / 2];

// ---- f32x2 packed-math helpers -------------------------------------------
union f2u { float2 f; unsigned long long u; };

__device__ __forceinline__ float2 f2fma(float2 a, float2 b, float2 c) {
    f2u A{a}, B{b}, C{c}, R;
    asm("fma.rn.f32x2 %0, %1, %2, %3;" : "=l"(R.u) : "l"(A.u), "l"(B.u), "l"(C.u));
    return R.f;
}
__device__ __forceinline__ float2 f2mul(float2 a, float2 b) {
    f2u A{a}, B{b}, R;
    asm("mul.rn.f32x2 %0, %1, %2;" : "=l"(R.u) : "l"(A.u), "l"(B.u));
    return R.f;
}
__device__ __forceinline__ float2 f2add(float2 a, float2 b) {
    f2u A{a}, B{b}, R;
    asm("add.rn.f32x2 %0, %1, %2;" : "=l"(R.u) : "l"(A.u), "l"(B.u));
    return R.f;
}

// ---- pack: one thread per ROW-PAIR ---------------------------------------
__global__ void pack_kernel(const float* __restrict__ pts,
                            const float* __restrict__ pd,
                            const float* __restrict__ lin, int BN) {
    int q = blockIdx.x * blockDim.x + threadIdx.x;
    if (q * 2 >= BN) return;
    float px[2], py[2], pz[2], tx[2], ty[2], tz[2], l[2];
    float sq[2], tn2[2], pdself[2];
#pragma unroll
    for (int h = 0; h < 2; h++) {
        int n = 2 * q + h;
        px[h] = pts[3 * n + 0]; py[h] = pts[3 * n + 1]; pz[h] = pts[3 * n + 2];
        tx[h] = pd[3 * n + 0];  ty[h] = pd[3 * n + 1];  tz[h] = pd[3 * n + 2];
        l[h]  = lin[n];
        sq[h]     = fmaf(px[h], px[h], fmaf(py[h], py[h], pz[h] * pz[h]));
        tn2[h]    = fmaf(tx[h], tx[h], fmaf(ty[h], ty[h], tz[h] * tz[h]));
        pdself[h] = fmaf(px[h], tx[h], fmaf(py[h], ty[h], pz[h] * tz[h]));
        g_pack[n] = make_float4(px[h], py[h], pz[h], sq[h]);
    }
    RowPair r;
    r.q0 = make_float4(-tx[0], -tx[1], -ty[0], -ty[1]);
    r.q1 = make_float4(-tz[0], -tz[1], pdself[0], pdself[1]);
    r.q2 = make_float4(-2.f * px[0], -2.f * px[1], -2.f * py[0], -2.f * py[1]);
    r.q3 = make_float4(-2.f * pz[0], -2.f * pz[1], sq[0], sq[1]);
    r.q4 = make_float4(tn2[0] - 2.f, tn2[1] - 2.f,
                       2.f * (1.f + l[0]), 2.f * (1.f + l[1]));
    r.q5 = make_float4(0.5f * (1.f - l[0]), 0.5f * (1.f - l[1]), 0.f, 0.f);
    g_rp[q] = r;
}

constexpr int TI      = 16;            // i-rows per block (8 row-pairs)
constexpr int THREADS = 256;
constexpr int TJ      = 4;             // consecutive j-cols per thread
constexpr int JSPAN   = THREADS * TJ;  // 1024 cols per block

__global__ __launch_bounds__(THREADS)
void dist_kernel(float* __restrict__ out, int N) {
    const int b    = blockIdx.z;
    const int i0   = blockIdx.y * TI;
    const int j0   = blockIdx.x * JSPAN + threadIdx.x * TJ;  // 4 consecutive
    const int base = b * N;

    // j-tile: 4 consecutive float4 loads (64B/thread), then hoisted {v,v} packs
    float2 xp[TJ], yp[TJ], zp[TJ], wp[TJ];
#pragma unroll
    for (int jj = 0; jj < TJ; jj++) {
        float4 p = g_pack[base + j0 + jj];
        xp[jj] = make_float2(p.x, p.x);
        yp[jj] = make_float2(p.y, p.y);
        zp[jj] = make_float2(p.z, p.z);
        wp[jj] = make_float2(p.w, p.w);
    }

    const int pbase = (base + i0) >> 1;           // row-pair index
    size_t orow = ((size_t)b * N + (size_t)i0) * (size_t)N + (size_t)j0;

#pragma unroll 2
    for (int ii = 0; ii < TI / 2; ii++) {
        // Uniform-address 96B load -> L1 broadcast, pre-packed constants
        const RowPair c = g_rp[pbase + ii];
        const float2 Ax = make_float2(c.q0.x, c.q0.y);
        const float2 Ay = make_float2(c.q0.z, c.q0.w);
        const float2 Az = make_float2(c.q1.x, c.q1.y);
        const float2 Aw = make_float2(c.q1.z, c.q1.w);
        const float2 Bx = make_float2(c.q2.x, c.q2.y);
        const float2 By = make_float2(c.q2.z, c.q2.w);
        const float2 Bz = make_float2(c.q3.x, c.q3.y);
        const float2 Bw = make_float2(c.q3.z, c.q3.w);
        const float2 Cx = make_float2(c.q4.x, c.q4.y);
        const float2 al = make_float2(c.q4.z, c.q4.w);
        const float2 be = make_float2(c.q5.x, c.q5.y);

        float o0[TJ], o1[TJ];
#pragma unroll
        for (int jj = 0; jj < TJ; jj++) {
            // along_i = p_j.(-t_i) + p_i.t_i   (packed over the 2 rows)
            float2 a2v = f2fma(xp[jj], Ax, f2fma(yp[jj], Ay, f2fma(zp[jj], Az, Aw)));
            // sqd_i = p_j.(-2p_i) + |p_i|^2 + |p_j|^2
            float2 sqd = f2fma(xp[jj], Bx,
                         f2fma(yp[jj], By,
                         f2fma(zp[jj], Bz, f2add(Bw, wp[jj]))));
            float2 a2 = f2mul(a2v, a2v);
            float2 t  = f2fma(a2, Cx, sqd);
            float n0 = fmaxf(t.x, 0.0f), n1 = fmaxf(t.y, 0.0f);
            o0[jj] = fmaf(al.x, n0, be.x * a2.x);
            o1[jj] = fmaf(al.y, n1, be.y * a2.y);
        }
        // One coalesced streaming STG.128 per row (write-once output)
        __stcs(reinterpret_cast<float4*>(out + orow),
               make_float4(o0[0], o0[1], o0[2], o0[3]));
        __stcs(reinterpret_cast<float4*>(out + orow + N),
               make_float4(o1[0], o1[1], o1[2], o1[3]));
        orow += 2 * (size_t)N;
    }
}

// Fallback for shapes not divisible by the tile (not expected for N=8192).
__global__ void dist_kernel_generic(float* __restrict__ out, int N, int Btot) {
    int64_t idx = (int64_t)blockIdx.x * blockDim.x + threadIdx.x;
    int64_t total = (int64_t)Btot * N * N;
    if (idx >= total) return;
    int j = (int)(idx % N);
    int64_t t = idx / N;
    int i = (int)(t % N);
    int b = (int)(t / N);
    int row = b * N + i;
    const RowPair c = g_rp[row >> 1];
    int h = row & 1;
    float Ax = h ? c.q0.y : c.q0.x, Ay = h ? c.q0.w : c.q0.z;
    float Az = h ? c.q1.y : c.q1.x, Aw = h ? c.q1.w : c.q1.z;
    float Bx = h ? c.q2.y : c.q2.x, By = h ? c.q2.w : c.q2.z;
    float Bz = h ? c.q3.y : c.q3.x, Bw = h ? c.q3.w : c.q3.z;
    float Cx = h ? c.q4.y : c.q4.x, al = h ? c.q4.w : c.q4.z;
    float be = h ? c.q5.y : c.q5.x;
    float4 p = g_pack[b * N + j];
    float along = fmaf(p.x, Ax, fmaf(p.y, Ay, fmaf(p.z, Az, Aw)));
    float sqd   = fmaf(p.x, Bx, fmaf(p.y, By, fmaf(p.z, Bz, Bw + p.w)));
    float a2    = along * along;
    float nrm   = fmaxf(fmaf(a2, Cx, sqd), 0.0f);
    out[idx]    = fmaf(al, nrm, be * a2);
}

extern "C" void kernel_launch(void* const* d_in, const int* in_sizes, int n_in,
                              void* d_out, int out_size) {
    const float* points = (const float*)d_in[0];
    const float* pdir   = (const float*)d_in[1];
    const float* lin    = (const float*)d_in[2];
    float* out = (float*)d_out;

    const int BN = in_sizes[2];              // B*N (linearity has 1 elem/point)
    const int N  = (int)((long long)out_size / BN);
    const int B  = BN / N;

    int pairs = (BN + 1) / 2;
    pack_kernel<<<(pairs + 255) / 256, 256>>>(points, pdir, lin, BN);

    if ((N % JSPAN) == 0 && (N % TI) == 0) {
        dim3 grid(N / JSPAN, N / TI, B);
        dist_kernel<<<grid, THREADS>>>(out, N);
    } else {
        int64_t total = (int64_t)B * N * N;
        int64_t blocks = (total + 255) / 256;
        dist_kernel_generic<<<(unsigned)blocks, 256>>>(out, N, B);
    }
}

// round 10
// speedup vs baseline: 1.1361x; 1.1361x over previous
#include <cuda_runtime.h>
#include <cstdint>

// ---------------------------------------------------------------------------
// AnisotropicDistance: out[b,i,j] = alpha_i * max(||d||^2 + a^2*(|t_i|^2-2), 0)
//                                 + beta_i * a^2,  d = p_i - p_j, a = d . t_i
// B=2, N=8192 -> 537MB fp32 output: DRAM-write bound.
// R7: SoA j-pack (x[],y[],z[],|p|^2[]) so a thread owning 4 CONSECUTIVE cols
//     gets coalesced LDG.128 loads AND a single STG.128 streaming store per
//     row. Scalar math (f32x2 failed in R6: broadcast packs cost 2 MOVs + 2
//     regs each -> occupancy collapse). TI=32 halves j-load amortized cost.
// ---------------------------------------------------------------------------

#define MAX_BN 32768

// SoA j-side data (component arrays -> coalesced float4 loads of 4 cols)
__device__ float g_px[MAX_BN];
__device__ float g_py[MAX_BN];
__device__ float g_pz[MAX_BN];
__device__ float g_pw[MAX_BN];   // |p|^2

// Per-row constants (uniform broadcast loads)
__device__ float4 g_q0[MAX_BN];  // (-tx, -ty, -tz, p.t)
__device__ float4 g_q1[MAX_BN];  // (-2px, -2py, -2pz, |p|^2)
__device__ float4 g_q2[MAX_BN];  // (|t|^2-2, alpha, beta, 0)

__global__ void pack_kernel(const float* __restrict__ pts,
                            const float* __restrict__ pd,
                            const float* __restrict__ lin, int BN) {
    int n = blockIdx.x * blockDim.x + threadIdx.x;
    if (n >= BN) return;
    float px = pts[3 * n + 0], py = pts[3 * n + 1], pz = pts[3 * n + 2];
    float tx = pd[3 * n + 0],  ty = pd[3 * n + 1],  tz = pd[3 * n + 2];
    float l  = lin[n];
    float sq     = fmaf(px, px, fmaf(py, py, pz * pz));
    float tn2    = fmaf(tx, tx, fmaf(ty, ty, tz * tz));
    float pdself = fmaf(px, tx, fmaf(py, ty, pz * tz));
    g_px[n] = px; g_py[n] = py; g_pz[n] = pz; g_pw[n] = sq;
    g_q0[n] = make_float4(-tx, -ty, -tz, pdself);
    g_q1[n] = make_float4(-2.0f * px, -2.0f * py, -2.0f * pz, sq);
    g_q2[n] = make_float4(tn2 - 2.0f, 2.0f * (1.0f + l), 0.5f * (1.0f - l), 0.0f);
}

constexpr int TI      = 32;            // i-rows per block
constexpr int THREADS = 256;
constexpr int TJ      = 4;             // consecutive j-cols per thread
constexpr int JSPAN   = THREADS * TJ;  // 1024 cols per block

__global__ __launch_bounds__(THREADS, 6)
void dist_kernel(float* __restrict__ out, int N) {
    const int b    = blockIdx.z;
    const int i0   = blockIdx.y * TI;
    const int j0   = blockIdx.x * JSPAN + threadIdx.x * TJ;  // 4 consecutive
    const int base = b * N;

    // j-tile: 4 coalesced LDG.128 (16B inter-thread stride) from SoA arrays.
    const float4 X = *reinterpret_cast<const float4*>(&g_px[base + j0]);
    const float4 Y = *reinterpret_cast<const float4*>(&g_py[base + j0]);
    const float4 Z = *reinterpret_cast<const float4*>(&g_pz[base + j0]);
    const float4 W = *reinterpret_cast<const float4*>(&g_pw[base + j0]);

    size_t orow = ((size_t)b * N + (size_t)i0) * (size_t)N + (size_t)j0;

#pragma unroll 4
    for (int ii = 0; ii < TI; ii++) {
        // Uniform-address loads -> L1 broadcast, L2 resident.
        const int   r = base + i0 + ii;
        const float4 A  = g_q0[r];
        const float4 Bv = g_q1[r];
        const float4 C  = g_q2[r];

        float o[TJ];
#define COL(k, cx, cy, cz, cw)                                              \
        {                                                                    \
            float along = fmaf(cx, A.x, fmaf(cy, A.y, fmaf(cz, A.z, A.w))); \
            float sqd = fmaf(cx, Bv.x,                                      \
                        fmaf(cy, Bv.y,                                      \
                        fmaf(cz, Bv.z, Bv.w + cw)));                        \
            float a2  = along * along;                                       \
            float nrm = fmaxf(fmaf(a2, C.x, sqd), 0.0f);                     \
            o[k] = fmaf(C.y, nrm, C.z * a2);                                 \
        }
        COL(0, X.x, Y.x, Z.x, W.x)
        COL(1, X.y, Y.y, Z.y, W.y)
        COL(2, X.z, Y.z, Z.z, W.z)
        COL(3, X.w, Y.w, Z.w, W.w)
#undef COL
        // One coalesced streaming STG.128 per row (write-once output).
        __stcs(reinterpret_cast<float4*>(out + orow),
               make_float4(o[0], o[1], o[2], o[3]));
        orow += N;
    }
}

// Fallback for shapes not divisible by the tile (not expected for N=8192).
__global__ void dist_kernel_generic(float* __restrict__ out, int N, int Btot) {
    int64_t idx = (int64_t)blockIdx.x * blockDim.x + threadIdx.x;
    int64_t total = (int64_t)Btot * N * N;
    if (idx >= total) return;
    int j = (int)(idx % N);
    int64_t t = idx / N;
    int i = (int)(t % N);
    int b = (int)(t / N);
    int r = b * N + i;
    float4 A  = g_q0[r];
    float4 Bv = g_q1[r];
    float4 C  = g_q2[r];
    int jj = b * N + j;
    float px = g_px[jj], py = g_py[jj], pz = g_pz[jj], pw = g_pw[jj];
    float along = fmaf(px, A.x, fmaf(py, A.y, fmaf(pz, A.z, A.w)));
    float sqd   = fmaf(px, Bv.x, fmaf(py, Bv.y, fmaf(pz, Bv.z, Bv.w + pw)));
    float a2    = along * along;
    float nrm   = fmaxf(fmaf(a2, C.x, sqd), 0.0f);
    out[idx]    = fmaf(C.y, nrm, C.z * a2);
}

extern "C" void kernel_launch(void* const* d_in, const int* in_sizes, int n_in,
                              void* d_out, int out_size) {
    const float* points = (const float*)d_in[0];
    const float* pdir   = (const float*)d_in[1];
    const float* lin    = (const float*)d_in[2];
    float* out = (float*)d_out;

    const int BN = in_sizes[2];              // B*N (linearity has 1 elem/point)
    const int N  = (int)((long long)out_size / BN);
    const int B  = BN / N;

    pack_kernel<<<(BN + 255) / 256, 256>>>(points, pdir, lin, BN);

    if ((N % JSPAN) == 0 && (N % TI) == 0) {
        dim3 grid(N / JSPAN, N / TI, B);
        dist_kernel<<<grid, THREADS>>>(out, N);
    } else {
        int64_t total = (int64_t)B * N * N;
        int64_t blocks = (total + 255) / 256;
        dist_kernel_generic<<<(unsigned)blocks, 256>>>(out, N, B);
    }
}